// round 16
// baseline (speedup 1.0000x reference)
#include <cuda_runtime.h>
#include <cstdint>

using u32 = unsigned int;
using u64 = unsigned long long;
#define FULL 0xffffffffu
#define NW 3             // warps per block
#define WSPAN3 3264      // per-warp hidden stage: 3 tiles x 16 rows x 68
#define XSPAN 768        // per-warp x stage: 2 buf x 3 tiles x 128

__device__ __forceinline__ float tanha(float x) {
    float y; asm("tanh.approx.f32 %0, %1;" : "=f"(y) : "f"(x)); return y;
}
__device__ __forceinline__ u32 t32(float v) {
    u32 r; asm("cvt.rna.tf32.f32 %0, %1;" : "=r"(r) : "f"(v)); return r;
}
__device__ __forceinline__ u64 pk2(float lo, float hi) {
    u64 r; asm("mov.b64 %0, {%1, %2};" : "=l"(r) : "f"(lo), "f"(hi)); return r;
}
__device__ __forceinline__ void up2(u64 v, float& a, float& b) {
    asm("mov.b64 {%0, %1}, %2;" : "=f"(a), "=f"(b) : "l"(v));
}
__device__ __forceinline__ u64 fma2(u64 a, u64 b, u64 c) {
    u64 d; asm("fma.rn.f32x2 %0, %1, %2, %3;" : "=l"(d) : "l"(a), "l"(b), "l"(c)); return d;
}

// d = a(16x8 tf32) @ b(8x8 tf32) + c
__device__ __forceinline__ void mma8(float d[4], const u32 a[4], const u32 b[2],
                                     const float c[4]) {
    asm("mma.sync.aligned.m16n8k8.row.col.f32.tf32.tf32.f32 "
        "{%0,%1,%2,%3}, {%4,%5,%6,%7}, {%8,%9}, {%10,%11,%12,%13};"
        : "=f"(d[0]), "=f"(d[1]), "=f"(d[2]), "=f"(d[3])
        : "r"(a[0]), "r"(a[1]), "r"(a[2]), "r"(a[3]),
          "r"(b[0]), "r"(b[1]),
          "f"(c[0]), "f"(c[1]), "f"(c[2]), "f"(c[3]));
}

__device__ __forceinline__ void cp16(float* dst_smem, const float* src) {
    u32 daddr = (u32)__cvta_generic_to_shared(dst_smem);
    asm volatile("cp.async.cg.shared.global [%0], [%1], 16;\n"
                 "cp.async.commit_group;" :: "r"(daddr), "l"(src) : "memory");
}

// Accumulator position p holds h component pi(p): lane accum slots == next-step
// A-frag slots, so the recurrence needs no shuffles.
__device__ __forceinline__ int pi_map(int p) {
    return (p < 8) ? ((p >> 1) | ((p & 1) << 2))
                   : (8 | (((p - 8) >> 1)) | ((p & 1) << 2));
}

// B (h-part only) element: col = permuted output col (0..47), k = 0..15
__device__ __forceinline__ float bval_h(const float* w_hh, int col, int k) {
    int grp = col >> 4;
    int g = pi_map(col & 15) + grp * 16;
    return w_hh[g * 16 + k];
}

__global__ void __launch_bounds__(96, 3)
gru_adder_kernel(const float* __restrict__ x,
                 const float* __restrict__ w_ih,   // [48,2]
                 const float* __restrict__ w_hh,   // [48,16]
                 const float* __restrict__ b_ih,   // [48]
                 const float* __restrict__ b_hh,   // [48]
                 const float* __restrict__ w_sum,  // [16]
                 const float* __restrict__ b_sum,  // [1]
                 const float* __restrict__ w_car,  // [16]
                 const float* __restrict__ b_car,  // [1]
                 float* __restrict__ out_hidden,   // [B,4,16]
                 float* __restrict__ out_sums,     // [B,4]
                 float* __restrict__ out_carry,    // [B]
                 float* __restrict__ out_ol,       // [B,5]
                 int Bn)
{
    __shared__ float sb[NW * WSPAN3];
    __shared__ float sx[NW * XSPAN];

    const int warp = threadIdx.x >> 5;
    const int l = threadIdx.x & 31;
    const int q = l & 3;      // lane quad position
    const int a = l >> 2;     // row group: rows a and a+8

    float* swh0 = sb + warp * WSPAN3;          // tile A hidden stage
    float* swh1 = swh0 + 1088;                 // tile B
    float* swh2 = swh1 + 1088;                 // tile C
    float* sxw  = sx + warp * XSPAN;

    // ---------- per-lane B fragments (single tf32), h-chunks only ----------
    // r/z tiles PRESCALED by 0.5: sig(x) = 0.5*tanh(0.5x)+0.5
    u32 Bh[4][2][2];
#pragma unroll
    for (int nt = 0; nt < 4; nt++) {
#pragma unroll
        for (int kc = 0; kc < 2; kc++) {
            int col = nt * 8 + a;
            Bh[nt][kc][0] = t32(0.5f * bval_h(w_hh, col, kc * 8 + q));
            Bh[nt][kc][1] = t32(0.5f * bval_h(w_hh, col, kc * 8 + q + 4));
        }
    }
    u32 Hh[2][2][2];
#pragma unroll
    for (int ti = 0; ti < 2; ti++) {
#pragma unroll
        for (int kc = 0; kc < 2; kc++) {
            int col = 32 + ti * 8 + a;
            Hh[ti][kc][0] = t32(bval_h(w_hh, col, kc * 8 + q));
            Hh[ti][kc][1] = t32(bval_h(w_hh, col, kc * 8 + q + 4));
        }
    }
    // sum/carry projection tile: col 0 = w_sum, col 1 = w_car, cols 2..7 = 0
    u32 BS[2][2];
#pragma unroll
    for (int kc = 0; kc < 2; kc++) {
        float v0 = 0.0f, v1 = 0.0f;
        if (a == 0) { v0 = w_sum[kc * 8 + q]; v1 = w_sum[kc * 8 + q + 4]; }
        if (a == 1) { v0 = w_car[kc * 8 + q]; v1 = w_car[kc * 8 + q + 4]; }
        BS[kc][0] = t32(v0);
        BS[kc][1] = t32(v1);
    }

    // ---------- per-lane x weights, packed over pr; rz prescaled 0.5 ----------
    u64 wxp0[6], wxp1[6];
#pragma unroll
    for (int nt = 0; nt < 4; nt++) {
        int c0 = nt * 8 + 2 * q, c1 = c0 + 1;
        int g0 = pi_map(c0 & 15) + (c0 >> 4) * 16;
        int g1 = pi_map(c1 & 15) + (c1 >> 4) * 16;
        wxp0[nt] = pk2(0.5f * w_ih[g0 * 2],     0.5f * w_ih[g1 * 2]);
        wxp1[nt] = pk2(0.5f * w_ih[g0 * 2 + 1], 0.5f * w_ih[g1 * 2 + 1]);
    }
#pragma unroll
    for (int ti = 0; ti < 2; ti++) {
        int c0 = (6 + ti) * 8 + 2 * q, c1 = c0 + 1;
        int g0 = pi_map(c0 & 15) + 32;
        int g1 = pi_map(c1 & 15) + 32;
        wxp0[4 + ti] = pk2(w_ih[g0 * 2],     w_ih[g1 * 2]);
        wxp1[4 + ti] = pk2(w_ih[g0 * 2 + 1], w_ih[g1 * 2 + 1]);
    }

    // ---------- per-lane bias init, packed over pr; rz prescaled 0.5 ----------
    u64 cbp[8];
#pragma unroll
    for (int nt = 0; nt < 8; nt++) {
        float vv[2];
#pragma unroll
        for (int pr = 0; pr < 2; pr++) {
            int col = nt * 8 + 2 * q + pr;
            int grp = col >> 4;
            int g = pi_map(col & 15);
            if (grp == 0)      vv[pr] = 0.5f * (b_ih[g] + b_hh[g]);
            else if (grp == 1) vv[pr] = 0.5f * (b_ih[16 + g] + b_hh[16 + g]);
            else if (grp == 2) vv[pr] = b_hh[32 + g];
            else               vv[pr] = b_ih[32 + g];
        }
        cbp[nt] = pk2(vv[0], vv[1]);
    }

    const float bs = b_sum[0];
    const float bc = b_car[0];

    // one GRU step for one 16-row tile (fully inlined; all indices constant)
    auto step = [&](int t, const float* xs0, const float* xs1,
                    float* hr0, float* hr1, u32 (&ahh)[2][4],
                    float* su0, float* su1, float& ca0, float& ca1,
                    float* swh_) {
        const u64 xd00 = pk2(xs0[2 * t], xs0[2 * t]);
        const u64 xd01 = pk2(xs0[2 * t + 1], xs0[2 * t + 1]);
        const u64 xd10 = pk2(xs1[2 * t], xs1[2 * t]);
        const u64 xd11 = pk2(xs1[2 * t + 1], xs1[2 * t + 1]);

        float acc[6][4];
#pragma unroll
        for (int nt = 0; nt < 4; nt++) {
            u64 p0 = fma2(wxp1[nt], xd01, fma2(wxp0[nt], xd00, cbp[nt]));
            u64 p1 = fma2(wxp1[nt], xd11, fma2(wxp0[nt], xd10, cbp[nt]));
            up2(p0, acc[nt][0], acc[nt][1]);
            up2(p1, acc[nt][2], acc[nt][3]);
        }
#pragma unroll
        for (int ti = 0; ti < 2; ti++) {
            up2(cbp[4 + ti], acc[4 + ti][0], acc[4 + ti][1]);
            acc[4 + ti][2] = acc[4 + ti][0];
            acc[4 + ti][3] = acc[4 + ti][1];
        }
        float in0[4], in1[4];
#pragma unroll
        for (int ti = 0; ti < 2; ti++) {
            u64 p0 = fma2(wxp1[4 + ti], xd01, fma2(wxp0[4 + ti], xd00, cbp[6 + ti]));
            u64 p1 = fma2(wxp1[4 + ti], xd11, fma2(wxp0[4 + ti], xd10, cbp[6 + ti]));
            up2(p0, in0[ti * 2], in0[ti * 2 + 1]);
            up2(p1, in1[ti * 2], in1[ti * 2 + 1]);
        }

        if (t > 0) {
#pragma unroll
            for (int nt = 0; nt < 4; nt++) {
#pragma unroll
                for (int kc = 0; kc < 2; kc++)
                    mma8(acc[nt], ahh[kc], Bh[nt][kc], acc[nt]);
            }
#pragma unroll
            for (int ti = 0; ti < 2; ti++) {
#pragma unroll
                for (int kc = 0; kc < 2; kc++)
                    mma8(acc[4 + ti], ahh[kc], Hh[ti][kc], acc[4 + ti]);
            }
        }

        // prescaled activations + h update
        //   r*hn = 0.5*(hn + tr*hn); h' = n + 0.5*(d + tz*d), d = h-n
#pragma unroll
        for (int m = 0; m < 4; m++) {
            const int toff = m >> 1, pr = m & 1;
            {
                float tr = tanha(acc[toff][pr]);
                float tz = tanha(acc[2 + toff][pr]);
                float hn = acc[4 + toff][pr];
                float n = tanha(fmaf(0.5f, fmaf(tr, hn, hn), in0[toff * 2 + pr]));
                float d = hr0[m] - n;
                hr0[m] = fmaf(0.5f, fmaf(tz, d, d), n);
            }
            {
                float tr = tanha(acc[toff][2 + pr]);
                float tz = tanha(acc[2 + toff][2 + pr]);
                float hn = acc[4 + toff][2 + pr];
                float n = tanha(fmaf(0.5f, fmaf(tr, hn, hn), in1[toff * 2 + pr]));
                float d = hr1[m] - n;
                hr1[m] = fmaf(0.5f, fmaf(tz, d, d), n);
            }
            const int col = q + ((m & 1) << 2) + ((m >> 1) << 3);
            swh_[a * 68 + t * 16 + col] = hr0[m];
            swh_[(a + 8) * 68 + t * 16 + col] = hr1[m];
        }

        // A-frag of new h (feeds sum MMA now, gates next step)
#pragma unroll
        for (int kc = 0; kc < 2; kc++) {
            ahh[kc][0] = t32(hr0[2 * kc]);
            ahh[kc][1] = t32(hr1[2 * kc]);
            ahh[kc][2] = t32(hr0[2 * kc + 1]);
            ahh[kc][3] = t32(hr1[2 * kc + 1]);
        }

        // sum/carry logits via MMA (q==0 lanes hold cols 0,1)
        float accS[4] = {bs, bc, bs, bc};
        mma8(accS, ahh[0], BS[0], accS);
        mma8(accS, ahh[1], BS[1], accS);
        su0[t] = accS[0];
        su1[t] = accS[2];
        ca0 = accS[1];
        ca1 = accS[3];
    };

    // logit + hidden writeback for one tile
    auto writeback = [&](int e0, const float* su0, const float* su1,
                         float ca0, float ca1, float* swh_) {
        if (q == 0) {
            const int er0 = e0 + a, er1 = e0 + a + 8;
            float4 s4a = make_float4(su0[0], su0[1], su0[2], su0[3]);
            float4 s4b = make_float4(su1[0], su1[1], su1[2], su1[3]);
            *reinterpret_cast<float4*>(out_sums + (size_t)er0 * 4) = s4a;
            *reinterpret_cast<float4*>(out_sums + (size_t)er1 * 4) = s4b;
            out_carry[er0] = ca0;
            out_carry[er1] = ca1;
            float* o0 = out_ol + (size_t)er0 * 5;
            o0[0] = s4a.x; o0[1] = s4a.y; o0[2] = s4a.z; o0[3] = s4a.w; o0[4] = ca0;
            float* o1 = out_ol + (size_t)er1 * 5;
            o1[0] = s4b.x; o1[1] = s4b.y; o1[2] = s4b.z; o1[3] = s4b.w; o1[4] = ca1;
        }
        float4* oh4 = reinterpret_cast<float4*>(out_hidden + (size_t)e0 * 64);
#pragma unroll
        for (int i = 0; i < 8; i++) {
            int idx = i * 32 + l;
            int row = idx >> 4, c4 = idx & 15;
            oh4[idx] = *reinterpret_cast<float4*>(swh_ + row * 68 + c4 * 4);
        }
    };

    // ---------- persistent loop: each warp runs 3 tile streams ----------
    const int ntiles = Bn >> 4;
    const int T3 = (ntiles + 2) / 3;
    const int nwarp = blockDim.x >> 5;
    const int tstride = gridDim.x * nwarp;
    const int i0 = blockIdx.x * nwarp + warp;

    // prefetch first iteration's x (3 tiles)
    if (i0 < T3) {
        cp16(sxw + l * 4, x + (size_t)i0 * 128 + l * 4);
        if (i0 + T3 < ntiles)
            cp16(sxw + 128 + l * 4, x + (size_t)(i0 + T3) * 128 + l * 4);
        if (i0 + 2 * T3 < ntiles)
            cp16(sxw + 256 + l * 4, x + (size_t)(i0 + 2 * T3) * 128 + l * 4);
    }

    int buf = 0;
    for (int i = i0; i < T3; i += tstride) {
        const int tA = i, tB = i + T3, tC = i + 2 * T3;
        const bool vB = tB < ntiles, vC = tC < ntiles;

        asm volatile("cp.async.wait_group 0;" ::: "memory");
        __syncwarp();
        const float* xb = sxw + buf * 384;
        float xsA0[8], xsA1[8], xsB0[8], xsB1[8], xsC0[8], xsC1[8];
        {
            float4 v0 = *reinterpret_cast<const float4*>(xb + a * 8);
            float4 v1 = *reinterpret_cast<const float4*>(xb + a * 8 + 4);
            float4 v2 = *reinterpret_cast<const float4*>(xb + (a + 8) * 8);
            float4 v3 = *reinterpret_cast<const float4*>(xb + (a + 8) * 8 + 4);
            xsA0[0]=v0.x; xsA0[1]=v0.y; xsA0[2]=v0.z; xsA0[3]=v0.w;
            xsA0[4]=v1.x; xsA0[5]=v1.y; xsA0[6]=v1.z; xsA0[7]=v1.w;
            xsA1[0]=v2.x; xsA1[1]=v2.y; xsA1[2]=v2.z; xsA1[3]=v2.w;
            xsA1[4]=v3.x; xsA1[5]=v3.y; xsA1[6]=v3.z; xsA1[7]=v3.w;
        }
        if (vB) {
            float4 v0 = *reinterpret_cast<const float4*>(xb + 128 + a * 8);
            float4 v1 = *reinterpret_cast<const float4*>(xb + 128 + a * 8 + 4);
            float4 v2 = *reinterpret_cast<const float4*>(xb + 128 + (a + 8) * 8);
            float4 v3 = *reinterpret_cast<const float4*>(xb + 128 + (a + 8) * 8 + 4);
            xsB0[0]=v0.x; xsB0[1]=v0.y; xsB0[2]=v0.z; xsB0[3]=v0.w;
            xsB0[4]=v1.x; xsB0[5]=v1.y; xsB0[6]=v1.z; xsB0[7]=v1.w;
            xsB1[0]=v2.x; xsB1[1]=v2.y; xsB1[2]=v2.z; xsB1[3]=v2.w;
            xsB1[4]=v3.x; xsB1[5]=v3.y; xsB1[6]=v3.z; xsB1[7]=v3.w;
        }
        if (vC) {
            float4 v0 = *reinterpret_cast<const float4*>(xb + 256 + a * 8);
            float4 v1 = *reinterpret_cast<const float4*>(xb + 256 + a * 8 + 4);
            float4 v2 = *reinterpret_cast<const float4*>(xb + 256 + (a + 8) * 8);
            float4 v3 = *reinterpret_cast<const float4*>(xb + 256 + (a + 8) * 8 + 4);
            xsC0[0]=v0.x; xsC0[1]=v0.y; xsC0[2]=v0.z; xsC0[3]=v0.w;
            xsC0[4]=v1.x; xsC0[5]=v1.y; xsC0[6]=v1.z; xsC0[7]=v1.w;
            xsC1[0]=v2.x; xsC1[1]=v2.y; xsC1[2]=v2.z; xsC1[3]=v2.w;
            xsC1[4]=v3.x; xsC1[5]=v3.y; xsC1[6]=v3.z; xsC1[7]=v3.w;
        }
        __syncwarp();
        const int nxt = i + tstride;
        if (nxt < T3) {
            float* pb = sxw + (buf ^ 1) * 384;
            cp16(pb + l * 4, x + (size_t)nxt * 128 + l * 4);
            if (nxt + T3 < ntiles)
                cp16(pb + 128 + l * 4, x + (size_t)(nxt + T3) * 128 + l * 4);
            if (nxt + 2 * T3 < ntiles)
                cp16(pb + 256 + l * 4, x + (size_t)(nxt + 2 * T3) * 128 + l * 4);
        }
        buf ^= 1;

        float hrA0[4] = {0,0,0,0}, hrA1[4] = {0,0,0,0};
        float hrB0[4] = {0,0,0,0}, hrB1[4] = {0,0,0,0};
        float hrC0[4] = {0,0,0,0}, hrC1[4] = {0,0,0,0};
        u32 ahhA[2][4], ahhB[2][4], ahhC[2][4];
        float suA0[4], suA1[4], suB0[4], suB1[4], suC0[4], suC1[4];
        float caA0, caA1, caB0, caB1, caC0, caC1;

#pragma unroll
        for (int t = 0; t < 4; t++) {
            step(t, xsA0, xsA1, hrA0, hrA1, ahhA, suA0, suA1, caA0, caA1, swh0);
            if (vB) step(t, xsB0, xsB1, hrB0, hrB1, ahhB, suB0, suB1, caB0, caB1, swh1);
            if (vC) step(t, xsC0, xsC1, hrC0, hrC1, ahhC, suC0, suC1, caC0, caC1, swh2);
        }
        __syncwarp();

        writeback(tA * 16, suA0, suA1, caA0, caA1, swh0);
        if (vB) writeback(tB * 16, suB0, suB1, caB0, caB1, swh1);
        if (vC) writeback(tC * 16, suC0, suC1, caC0, caC1, swh2);

        __syncwarp();   // protect stage buffers before next iteration
    }
}

// ---------------- launch ----------------

extern "C" void kernel_launch(void* const* d_in, const int* in_sizes, int n_in,
                              void* d_out, int out_size)
{
    const float* x     = (const float*)d_in[0];
    const float* w_ih  = (const float*)d_in[1];
    const float* w_hh  = (const float*)d_in[2];
    const float* b_ih  = (const float*)d_in[3];
    const float* b_hh  = (const float*)d_in[4];
    const float* w_sum = (const float*)d_in[5];
    const float* b_sum = (const float*)d_in[6];
    const float* w_car = (const float*)d_in[7];
    const float* b_car = (const float*)d_in[8];

    const int B = in_sizes[0] / 8;   // x is [B, 4, 2]

    float* out = (float*)d_out;
    float* out_hidden = out;                              // B*64
    float* out_sums   = out_hidden + (size_t)B * 64;      // B*4
    float* out_carry  = out_sums + (size_t)B * 4;         // B
    float* out_ol     = out_carry + (size_t)B;            // B*5

    const int threads = 32 * NW;            // 3 warps/block, 3 blocks/SM
    const int ntiles = B / 16;
    const int T3 = (ntiles + 2) / 3;
    int blocks = 444;
    int maxb = (T3 + NW - 1) / NW;
    if (blocks > maxb) blocks = maxb;
    if (blocks < 1) blocks = 1;

    gru_adder_kernel<<<blocks, threads>>>(x, w_ih, w_hh, b_ih, b_hh,
                                          w_sum, b_sum, w_car, b_car,
                                          out_hidden, out_sums, out_carry,
                                          out_ol, B);
}

// round 17
// speedup vs baseline: 1.5805x; 1.5805x over previous
#include <cuda_runtime.h>
#include <cstdint>

using u32 = unsigned int;
using u64 = unsigned long long;
#define FULL 0xffffffffu
#define NW 7                  // warps per block
#define WARP_SPAN 3200        // floats: 2x1216 hidden stages + 768 x stage
#define TILE_SPAN 1216        // 16 rows x 76 (cols 64-67 su, 68 carry)
#define W_FLOATS 160          // block weight region: wxp 96 + cbp 64

__device__ __forceinline__ float tanha(float x) {
    float y; asm("tanh.approx.f32 %0, %1;" : "=f"(y) : "f"(x)); return y;
}
__device__ __forceinline__ u32 t32(float v) {
    u32 r; asm("cvt.rna.tf32.f32 %0, %1;" : "=r"(r) : "f"(v)); return r;
}
__device__ __forceinline__ u64 pk2(float lo, float hi) {
    u64 r; asm("mov.b64 %0, {%1, %2};" : "=l"(r) : "f"(lo), "f"(hi)); return r;
}
__device__ __forceinline__ void up2(u64 v, float& a, float& b) {
    asm("mov.b64 {%0, %1}, %2;" : "=f"(a), "=f"(b) : "l"(v));
}
__device__ __forceinline__ u64 fma2(u64 a, u64 b, u64 c) {
    u64 d; asm("fma.rn.f32x2 %0, %1, %2, %3;" : "=l"(d) : "l"(a), "l"(b), "l"(c)); return d;
}
// volatile shared loads: keep weight/x reads as per-step LDS (don't re-materialize regs)
__device__ __forceinline__ void lds128u2(u64& a, u64& b, u32 addr) {
    asm volatile("ld.shared.v2.u64 {%0, %1}, [%2];" : "=l"(a), "=l"(b) : "r"(addr));
}
__device__ __forceinline__ u64 lds64u(u32 addr) {
    u64 a; asm volatile("ld.shared.u64 %0, [%1];" : "=l"(a) : "r"(addr)); return a;
}
__device__ __forceinline__ void lds2v(float& x0, float& x1, u32 addr) {
    asm volatile("ld.shared.v2.f32 {%0, %1}, [%2];" : "=f"(x0), "=f"(x1) : "r"(addr));
}

// d = a(16x8 tf32) @ b(8x8 tf32) + c
__device__ __forceinline__ void mma8(float d[4], const u32 a[4], const u32 b[2],
                                     const float c[4]) {
    asm("mma.sync.aligned.m16n8k8.row.col.f32.tf32.tf32.f32 "
        "{%0,%1,%2,%3}, {%4,%5,%6,%7}, {%8,%9}, {%10,%11,%12,%13};"
        : "=f"(d[0]), "=f"(d[1]), "=f"(d[2]), "=f"(d[3])
        : "r"(a[0]), "r"(a[1]), "r"(a[2]), "r"(a[3]),
          "r"(b[0]), "r"(b[1]),
          "f"(c[0]), "f"(c[1]), "f"(c[2]), "f"(c[3]));
}

__device__ __forceinline__ void cp16(float* dst_smem, const float* src) {
    u32 daddr = (u32)__cvta_generic_to_shared(dst_smem);
    asm volatile("cp.async.cg.shared.global [%0], [%1], 16;\n"
                 "cp.async.commit_group;" :: "r"(daddr), "l"(src) : "memory");
}

// Accumulator position p holds h component pi(p): lane accum slots == next-step
// A-frag slots, so the recurrence needs no shuffles.
__device__ __forceinline__ int pi_map(int p) {
    return (p < 8) ? ((p >> 1) | ((p & 1) << 2))
                   : (8 | (((p - 8) >> 1)) | ((p & 1) << 2));
}
__device__ __forceinline__ float bval_h(const float* w_hh, int col, int k) {
    int grp = col >> 4;
    int g = pi_map(col & 15) + grp * 16;
    return w_hh[g * 16 + k];
}

__global__ void __launch_bounds__(224, 2)
gru_adder_kernel(const float* __restrict__ x,
                 const float* __restrict__ w_ih,   // [48,2]
                 const float* __restrict__ w_hh,   // [48,16]
                 const float* __restrict__ b_ih,   // [48]
                 const float* __restrict__ b_hh,   // [48]
                 const float* __restrict__ w_sum,  // [16]
                 const float* __restrict__ b_sum,  // [1]
                 const float* __restrict__ w_car,  // [16]
                 const float* __restrict__ b_car,  // [1]
                 float* __restrict__ out_hidden,   // [B,4,16]
                 float* __restrict__ out_sums,     // [B,4]
                 float* __restrict__ out_carry,    // [B]
                 float* __restrict__ out_ol,       // [B,5]
                 int Bn)
{
    extern __shared__ float sb[];

    const int tid = threadIdx.x;
    const int warp = tid >> 5;
    const int l = tid & 31;
    const int q = l & 3;      // lane quad position
    const int a = l >> 2;     // row group: rows a and a+8

    float* swh0 = sb + warp * WARP_SPAN;        // tile A hidden stage (16x76)
    float* swh1 = swh0 + TILE_SPAN;             // tile B hidden stage
    float* sxw  = swh1 + TILE_SPAN;             // x stage: 2buf x 2tiles x 16x12
    float* wsh  = sb + NW * WARP_SPAN;          // block weight region

    const u32 sxbase = (u32)__cvta_generic_to_shared(sxw);
    const u32 wbase  = (u32)__cvta_generic_to_shared(wsh);
    const u32 waddr  = wbase + q * 16;          // wxp pair base for this lane
    const u32 cbaddr = wbase + 384 + q * 8;     // cbp base for this lane

    // ---------- block weight region fill ----------
    // wxp layout: [nt(0..5)][q] float4 = (wxp0.lo, wxp0.hi, wxp1.lo, wxp1.hi)
    for (int idx = tid; idx < 24; idx += blockDim.x) {
        int nt = idx >> 2, qq = idx & 3;
        float4 v;
        if (nt < 4) {   // r/z: prescaled 0.5 (sig(x)=0.5*tanh(0.5x)+0.5)
            int c0 = nt * 8 + 2 * qq, c1 = c0 + 1;
            int g0 = pi_map(c0 & 15) + (c0 >> 4) * 16;
            int g1 = pi_map(c1 & 15) + (c1 >> 4) * 16;
            v = make_float4(0.5f * w_ih[g0 * 2],     0.5f * w_ih[g1 * 2],
                            0.5f * w_ih[g0 * 2 + 1], 0.5f * w_ih[g1 * 2 + 1]);
        } else {        // i_n tiles
            int ti = nt - 4;
            int c0 = (6 + ti) * 8 + 2 * qq, c1 = c0 + 1;
            int g0 = pi_map(c0 & 15) + 32;
            int g1 = pi_map(c1 & 15) + 32;
            v = make_float4(w_ih[g0 * 2],     w_ih[g1 * 2],
                            w_ih[g0 * 2 + 1], w_ih[g1 * 2 + 1]);
        }
        reinterpret_cast<float4*>(wsh)[idx] = v;
    }
    // cbp layout: [nt(0..7)][q] float2 = (bias col 2q, bias col 2q+1)
    for (int idx = tid; idx < 32; idx += blockDim.x) {
        int nt = idx >> 2, qq = idx & 3;
        float vv[2];
#pragma unroll
        for (int pr = 0; pr < 2; pr++) {
            int col = nt * 8 + 2 * qq + pr;
            int grp = col >> 4;
            int g = pi_map(col & 15);
            if (grp == 0)      vv[pr] = 0.5f * (b_ih[g] + b_hh[g]);
            else if (grp == 1) vv[pr] = 0.5f * (b_ih[16 + g] + b_hh[16 + g]);
            else if (grp == 2) vv[pr] = b_hh[32 + g];
            else               vv[pr] = b_ih[32 + g];
        }
        reinterpret_cast<float2*>(wsh + 96)[idx] = make_float2(vv[0], vv[1]);
    }
    __syncthreads();

    // ---------- per-lane MMA B fragments (registers) ----------
    u32 Bh[4][2][2];
#pragma unroll
    for (int nt = 0; nt < 4; nt++) {
#pragma unroll
        for (int kc = 0; kc < 2; kc++) {
            int col = nt * 8 + a;
            Bh[nt][kc][0] = t32(0.5f * bval_h(w_hh, col, kc * 8 + q));
            Bh[nt][kc][1] = t32(0.5f * bval_h(w_hh, col, kc * 8 + q + 4));
        }
    }
    u32 Hh[2][2][2];
#pragma unroll
    for (int ti = 0; ti < 2; ti++) {
#pragma unroll
        for (int kc = 0; kc < 2; kc++) {
            int col = 32 + ti * 8 + a;
            Hh[ti][kc][0] = t32(bval_h(w_hh, col, kc * 8 + q));
            Hh[ti][kc][1] = t32(bval_h(w_hh, col, kc * 8 + q + 4));
        }
    }
    u32 BS[2][2];
#pragma unroll
    for (int kc = 0; kc < 2; kc++) {
        float v0 = 0.0f, v1 = 0.0f;
        if (a == 0) { v0 = w_sum[kc * 8 + q]; v1 = w_sum[kc * 8 + q + 4]; }
        if (a == 1) { v0 = w_car[kc * 8 + q]; v1 = w_car[kc * 8 + q + 4]; }
        BS[kc][0] = t32(v0);
        BS[kc][1] = t32(v1);
    }
    const float bs = b_sum[0];
    const float bc = b_car[0];

    // one GRU step for one 16-row tile; weights/x read from shared each step
    auto step = [&](int t, u32 xA, float* hr0, float* hr1, u32 (&ahh)[2][4],
                    float* swh_) {
        float x00, x01, x10, x11;
        lds2v(x00, x01, xA + t * 8);          // row a
        lds2v(x10, x11, xA + 384 + t * 8);    // row a+8 (8 rows * 48B)
        const u64 xd00 = pk2(x00, x00);
        const u64 xd01 = pk2(x01, x01);
        const u64 xd10 = pk2(x10, x10);
        const u64 xd11 = pk2(x11, x11);

        float acc[6][4];
#pragma unroll
        for (int nt = 0; nt < 4; nt++) {
            u64 w0, w1;
            lds128u2(w0, w1, waddr + nt * 64);
            u64 cb = lds64u(cbaddr + nt * 32);
            u64 p0 = fma2(w1, xd01, fma2(w0, xd00, cb));
            u64 p1 = fma2(w1, xd11, fma2(w0, xd10, cb));
            up2(p0, acc[nt][0], acc[nt][1]);
            up2(p1, acc[nt][2], acc[nt][3]);
        }
        float in0[4], in1[4];
#pragma unroll
        for (int ti = 0; ti < 2; ti++) {
            u64 cbh = lds64u(cbaddr + (4 + ti) * 32);
            up2(cbh, acc[4 + ti][0], acc[4 + ti][1]);
            acc[4 + ti][2] = acc[4 + ti][0];
            acc[4 + ti][3] = acc[4 + ti][1];
            u64 w0, w1;
            lds128u2(w0, w1, waddr + (4 + ti) * 64);
            u64 cbi = lds64u(cbaddr + (6 + ti) * 32);
            u64 p0 = fma2(w1, xd01, fma2(w0, xd00, cbi));
            u64 p1 = fma2(w1, xd11, fma2(w0, xd10, cbi));
            up2(p0, in0[ti * 2], in0[ti * 2 + 1]);
            up2(p1, in1[ti * 2], in1[ti * 2 + 1]);
        }

        if (t > 0) {
#pragma unroll
            for (int nt = 0; nt < 4; nt++) {
#pragma unroll
                for (int kc = 0; kc < 2; kc++)
                    mma8(acc[nt], ahh[kc], Bh[nt][kc], acc[nt]);
            }
#pragma unroll
            for (int ti = 0; ti < 2; ti++) {
#pragma unroll
                for (int kc = 0; kc < 2; kc++)
                    mma8(acc[4 + ti], ahh[kc], Hh[ti][kc], acc[4 + ti]);
            }
        }

        // prescaled activations + h update:
        //   r*hn = 0.5*(hn + tr*hn); h' = n + 0.5*(d + tz*d), d = h-n
#pragma unroll
        for (int m = 0; m < 4; m++) {
            const int toff = m >> 1, pr = m & 1;
            {
                float tr = tanha(acc[toff][pr]);
                float tz = tanha(acc[2 + toff][pr]);
                float hn = acc[4 + toff][pr];
                float n = tanha(fmaf(0.5f, fmaf(tr, hn, hn), in0[toff * 2 + pr]));
                float d = hr0[m] - n;
                hr0[m] = fmaf(0.5f, fmaf(tz, d, d), n);
            }
            {
                float tr = tanha(acc[toff][2 + pr]);
                float tz = tanha(acc[2 + toff][2 + pr]);
                float hn = acc[4 + toff][2 + pr];
                float n = tanha(fmaf(0.5f, fmaf(tr, hn, hn), in1[toff * 2 + pr]));
                float d = hr1[m] - n;
                hr1[m] = fmaf(0.5f, fmaf(tz, d, d), n);
            }
            const int col = q + ((m & 1) << 2) + ((m >> 1) << 3);
            swh_[a * 76 + t * 16 + col] = hr0[m];
            swh_[(a + 8) * 76 + t * 16 + col] = hr1[m];
        }

        // A-frag of new h (feeds sum MMA now, gates next step)
#pragma unroll
        for (int kc = 0; kc < 2; kc++) {
            ahh[kc][0] = t32(hr0[2 * kc]);
            ahh[kc][1] = t32(hr1[2 * kc]);
            ahh[kc][2] = t32(hr0[2 * kc + 1]);
            ahh[kc][3] = t32(hr1[2 * kc + 1]);
        }

        // sum/carry logits via MMA; q==0 lanes stage them into the row pads
        float accS[4] = {bs, bc, bs, bc};
        mma8(accS, ahh[0], BS[0], accS);
        mma8(accS, ahh[1], BS[1], accS);
        if (q == 0) {
            swh_[a * 76 + 64 + t] = accS[0];
            swh_[(a + 8) * 76 + 64 + t] = accS[2];
            if (t == 3) {
                swh_[a * 76 + 68] = accS[1];
                swh_[(a + 8) * 76 + 68] = accS[3];
            }
        }
    };

    // writeback for one tile: everything staged in shared, coalesced out
    auto writeback = [&](int e0, float* swh_) {
#pragma unroll
        for (int i = 0; i < 2; i++) {
            int idx = i * 32 + l;
            out_sums[(size_t)e0 * 4 + idx] = swh_[(idx >> 2) * 76 + 64 + (idx & 3)];
        }
#pragma unroll
        for (int i = 0; i < 3; i++) {
            int idx = i * 32 + l;
            if (idx < 80) {
                int row = idx / 5, c = idx - row * 5;
                out_ol[(size_t)e0 * 5 + idx] = swh_[row * 76 + 64 + c];
            }
        }
        if (l < 16) out_carry[e0 + l] = swh_[l * 76 + 68];
        float4* oh4 = reinterpret_cast<float4*>(out_hidden + (size_t)e0 * 64);
#pragma unroll
        for (int i = 0; i < 8; i++) {
            int idx = i * 32 + l;
            int row = idx >> 4, c4 = idx & 15;
            oh4[idx] = *reinterpret_cast<float4*>(swh_ + row * 76 + c4 * 4);
        }
    };

    // x prefetch into pad-12 layout (row stride 48B: banks 12a%32 distinct)
    auto prefetch = [&](int st, int bufsel) {
#pragma unroll
        for (int h = 0; h < 2; h++) {
            int j = h * 32 + l;                 // chunk of 4 floats
            int tile = j >> 5, r2 = j & 31, row = r2 >> 1, half = r2 & 1;
            float* dst = sxw + bufsel * 384 + tile * 192 + row * 12 + half * 4;
            cp16(dst, x + (size_t)st * 256 + j * 4);
        }
    };

    // ---------- persistent loop over 32-row supertiles ----------
    const int nst = Bn >> 5;
    const int nwarp = blockDim.x >> 5;
    const int tstride = gridDim.x * nwarp;
    const int st0 = blockIdx.x * nwarp + warp;

    if (st0 < nst) prefetch(st0, 0);

    int buf = 0;
    for (int st = st0; st < nst; st += tstride) {
        const int e0 = st * 32;

        asm volatile("cp.async.wait_group 0;" ::: "memory");
        __syncwarp();
        const int nxt = st + tstride;
        if (nxt < nst) prefetch(nxt, buf ^ 1);

        const u32 xA = sxbase + (u32)(buf * 384 + a * 12) * 4;   // tile A row a
        const u32 xB = xA + 768;                                 // tile B (+192 floats)
        buf ^= 1;

        float hrA0[4] = {0,0,0,0}, hrA1[4] = {0,0,0,0};
        float hrB0[4] = {0,0,0,0}, hrB1[4] = {0,0,0,0};
        u32 ahhA[2][4], ahhB[2][4];

#pragma unroll
        for (int t = 0; t < 4; t++) {
            step(t, xA, hrA0, hrA1, ahhA, swh0);
            step(t, xB, hrB0, hrB1, ahhB, swh1);
        }
        __syncwarp();

        writeback(e0, swh0);
        writeback(e0 + 16, swh1);

        __syncwarp();   // protect stage buffers before next supertile
    }
}

// ---------------- launch ----------------

extern "C" void kernel_launch(void* const* d_in, const int* in_sizes, int n_in,
                              void* d_out, int out_size)
{
    const float* x     = (const float*)d_in[0];
    const float* w_ih  = (const float*)d_in[1];
    const float* w_hh  = (const float*)d_in[2];
    const float* b_ih  = (const float*)d_in[3];
    const float* b_hh  = (const float*)d_in[4];
    const float* w_sum = (const float*)d_in[5];
    const float* b_sum = (const float*)d_in[6];
    const float* w_car = (const float*)d_in[7];
    const float* b_car = (const float*)d_in[8];

    const int B = in_sizes[0] / 8;   // x is [B, 4, 2]

    float* out = (float*)d_out;
    float* out_hidden = out;                              // B*64
    float* out_sums   = out_hidden + (size_t)B * 64;      // B*4
    float* out_carry  = out_sums + (size_t)B * 4;         // B
    float* out_ol     = out_carry + (size_t)B;            // B*5

    const int threads = 32 * NW;            // 7 warps/block, 2 blocks/SM
    const int smem_bytes = (NW * WARP_SPAN + W_FLOATS) * 4;   // 90240 B

    cudaFuncSetAttribute(gru_adder_kernel,
                         cudaFuncAttributeMaxDynamicSharedMemorySize, smem_bytes);

    const int nst = B / 32;
    int blocks = 296;
    int maxb = (nst + NW - 1) / NW;
    if (blocks > maxb) blocks = maxb;
    if (blocks < 1) blocks = 1;

    gru_adder_kernel<<<blocks, threads, smem_bytes>>>(
        x, w_ih, w_hh, b_ih, b_hh, w_sum, b_sum, w_car, b_car,
        out_hidden, out_sums, out_carry, out_ol, B);
}